// round 1
// baseline (speedup 1.0000x reference)
#include <cuda_runtime.h>
#include <cuda_bf16.h>

#define FULL_MASK 0xFFFFFFFFu
#define TAGS 32
#define START 30
#define STOP 31

// scratch for per-batch partial scores (B=1024; padded for safety)
__device__ float g_partial[8192];

__global__ void __launch_bounds__(32, 16)
crf_nll_kernel(const float* __restrict__ feats,
               const float* __restrict__ trans,
               const int*   __restrict__ tags,
               const int*   __restrict__ lens,
               float*       __restrict__ partial,
               int B, int L)
{
    int b = blockIdx.x;
    if (b >= B) return;
    int lane = threadIdx.x;

    const float* fb = feats + (size_t)b * L * TAGS;
    const int*   tb = tags  + (size_t)b * L;
    int len = lens[b];

    // ---- load exp(transitions): lane j holds column j: E[i] = exp(trans[i][j])
    float E[TAGS];
#pragma unroll
    for (int i = 0; i < TAGS; ++i)
        E[i] = __expf(trans[i * TAGS + lane]);
    float estop = __expf(trans[lane * TAGS + STOP]);   // exp(trans[j][STOP])

    // ---- alpha0 = trans[START][j] + feats[b,0,j]; go to exp-domain
    float a0 = trans[START * TAGS + lane] + fb[lane];
    float m = a0;
#pragma unroll
    for (int o = 16; o; o >>= 1) m = fmaxf(m, __shfl_xor_sync(FULL_MASK, m, o));
    float p = __expf(a0 - m);
    float logscale = m;

    // ---- feat prefetch ring (4 steps ahead)
    float fq0 = (1 < len) ? fb[1 * TAGS + lane] : 0.f;
    float fq1 = (2 < len) ? fb[2 * TAGS + lane] : 0.f;
    float fq2 = (3 < len) ? fb[3 * TAGS + lane] : 0.f;
    float fq3 = (4 < len) ? fb[4 * TAGS + lane] : 0.f;

    // ---- forward recursion in exp-domain: p_new = (p . E) * exp(feat_t)
    for (int t = 1; t < len; ++t) {
        float f = __expf(fq0);
        fq0 = fq1; fq1 = fq2; fq2 = fq3;
        fq3 = (t + 4 < len) ? fb[(t + 4) * TAGS + lane] : 0.f;

        float s0 = 0.f, s1 = 0.f, s2 = 0.f, s3 = 0.f;
#pragma unroll
        for (int i = 0; i < TAGS; i += 4) {
            s0 = fmaf(__shfl_sync(FULL_MASK, p, i + 0), E[i + 0], s0);
            s1 = fmaf(__shfl_sync(FULL_MASK, p, i + 1), E[i + 1], s1);
            s2 = fmaf(__shfl_sync(FULL_MASK, p, i + 2), E[i + 2], s2);
            s3 = fmaf(__shfl_sync(FULL_MASK, p, i + 3), E[i + 3], s3);
        }
        p = ((s0 + s1) + (s2 + s3)) * f;

        // renormalize every 4 steps (keeps fp32 in range: growth <= ~e^10/step)
        if ((t & 3) == 0) {
            float mm = p;
#pragma unroll
            for (int o = 16; o; o >>= 1) mm = fmaxf(mm, __shfl_xor_sync(FULL_MASK, mm, o));
            p *= (1.0f / mm);
            logscale += __logf(mm);
        }
    }

    // ---- forward score: logscale + log(sum_j p_j * exp(trans[j][STOP]))
    float v = p * estop;
#pragma unroll
    for (int o = 16; o; o >>= 1) v += __shfl_xor_sync(FULL_MASK, v, o);
    float fwd = logscale + __logf(v);

    // ---- gold score
    // middle: sum over t in [0, len-2] of trans[tag_t][tag_{t+1}] + feats[b,t+1,tag_{t+1}]
    float midsum = 0.f;
    for (int t = lane; t < len - 1; t += 32) {
        int tg  = tb[t];
        int tg1 = tb[t + 1];
        midsum += trans[tg * TAGS + tg1] + fb[(t + 1) * TAGS + tg1];
    }
#pragma unroll
    for (int o = 16; o; o >>= 1) midsum += __shfl_xor_sync(FULL_MASK, midsum, o);

    if (lane == 0) {
        int tag0 = tb[0];
        int tend = tb[len - 1];
        float gold = trans[START * TAGS + tag0] + fb[tag0]   // begin
                   + trans[tend * TAGS + STOP]               // end
                   + midsum;                                 // middle
        partial[b] = fwd - gold;
    }
}

__global__ void reduce_kernel(const float* __restrict__ partial,
                              float* __restrict__ out, int B)
{
    __shared__ double s[256];
    int tid = threadIdx.x;
    double acc = 0.0;
    for (int i = tid; i < B; i += 256) acc += (double)partial[i];
    s[tid] = acc;
    __syncthreads();
#pragma unroll
    for (int w = 128; w; w >>= 1) {
        if (tid < w) s[tid] += s[tid + w];
        __syncthreads();
    }
    if (tid == 0) out[0] = (float)s[0];
}

extern "C" void kernel_launch(void* const* d_in, const int* in_sizes, int n_in,
                              void* d_out, int out_size)
{
    const float* feats = (const float*)d_in[0];
    const float* trans = (const float*)d_in[1];
    const int*   tags  = (const int*)d_in[2];
    const int*   lens  = (const int*)d_in[3];
    float* out = (float*)d_out;

    int B = in_sizes[3];                  // word_seq_lens: (B,)
    int L = in_sizes[2] / B;              // tags: (B, L)

    float* partial = nullptr;
    cudaGetSymbolAddress((void**)&partial, g_partial);

    crf_nll_kernel<<<B, 32>>>(feats, trans, tags, lens, partial, B, L);
    reduce_kernel<<<1, 256>>>(partial, out, B);
}

// round 2
// speedup vs baseline: 1.0847x; 1.0847x over previous
#include <cuda_runtime.h>
#include <cuda_bf16.h>

#define FULL_MASK 0xFFFFFFFFu
#define TAGS 32
#define START 30
#define STOP 31

// scratch for per-batch partial scores (B=1024; padded for safety)
__device__ float g_partial[8192];
__device__ int   g_count = 0;   // last-block-done counter (reset by reducer)

__global__ void __launch_bounds__(32, 16)
crf_nll_kernel(const float* __restrict__ feats,
               const float* __restrict__ trans,
               const int*   __restrict__ tags,
               const int*   __restrict__ lens,
               float* __restrict__ out,
               int B, int L)
{
    __shared__ float buf[2][TAGS];

    int b = blockIdx.x;
    int lane = threadIdx.x;

    const float* fb = feats + (size_t)b * L * TAGS;
    const int*   tb = tags  + (size_t)b * L;
    int len = lens[b];

    // ---- lane j holds E column j: E[i] = exp(trans[i][j])
    float E[TAGS];
#pragma unroll
    for (int i = 0; i < TAGS; ++i)
        E[i] = __expf(trans[i * TAGS + lane]);
    float estop = __expf(trans[lane * TAGS + STOP]);   // exp(trans[j][STOP])

    // ---- alpha0 = trans[START][j] + feats[b,0,j]; move to exp-domain
    float a0 = trans[START * TAGS + lane] + fb[lane];
    float m = a0;
#pragma unroll
    for (int o = 16; o; o >>= 1) m = fmaxf(m, __shfl_xor_sync(FULL_MASK, m, o));
    float p = __expf(a0 - m);
    float logscale = m;

    // ---- feat prefetch ring (4 steps ahead)
    float fq0 = (1 < len) ? fb[1 * TAGS + lane] : 0.f;
    float fq1 = (2 < len) ? fb[2 * TAGS + lane] : 0.f;
    float fq2 = (3 < len) ? fb[3 * TAGS + lane] : 0.f;
    float fq3 = (4 < len) ? fb[4 * TAGS + lane] : 0.f;

    // ---- forward recursion in exp-domain: p_new = (p . E) * exp(feat_t)
    // broadcast of p via double-buffered smem (8x LDS.128 instead of 32 SHFL)
    for (int t = 1; t < len; ++t) {
        float f = __expf(fq0);                // off the p-chain (fq0 prefetched)
        fq0 = fq1; fq1 = fq2; fq2 = fq3;
        fq3 = (t + 4 < len) ? fb[(t + 4) * TAGS + lane] : 0.f;

        int slot = t & 1;
        buf[slot][lane] = p;
        __syncwarp();
        const float4* bp = (const float4*)buf[slot];

        float a0_ = 0.f, a1_ = 0.f, a2_ = 0.f, a3_ = 0.f;
#pragma unroll
        for (int k = 0; k < 8; ++k) {
            float4 q = bp[k];
            a0_ = fmaf(q.x, E[4 * k + 0], a0_);
            a1_ = fmaf(q.y, E[4 * k + 1], a1_);
            a2_ = fmaf(q.z, E[4 * k + 2], a2_);
            a3_ = fmaf(q.w, E[4 * k + 3], a3_);
        }
        p = ((a0_ + a1_) + (a2_ + a3_)) * f;

        // renormalize every 8 steps (growth <= ~e^9.4/step; 8*9.4 < 88 -> safe)
        if ((t & 7) == 0) {
            float mm = p;
#pragma unroll
            for (int o = 16; o; o >>= 1) mm = fmaxf(mm, __shfl_xor_sync(FULL_MASK, mm, o));
            p *= (1.0f / mm);
            logscale += __logf(mm);
        }
    }

    // ---- forward score: logscale + log(sum_j p_j * exp(trans[j][STOP]))
    float v = p * estop;
#pragma unroll
    for (int o = 16; o; o >>= 1) v += __shfl_xor_sync(FULL_MASK, v, o);
    float fwd = logscale + __logf(v);

    // ---- gold score
    float midsum = 0.f;
    for (int t = lane; t < len - 1; t += 32) {
        int tg  = tb[t];
        int tg1 = tb[t + 1];
        midsum += trans[tg * TAGS + tg1] + fb[(t + 1) * TAGS + tg1];
    }
#pragma unroll
    for (int o = 16; o; o >>= 1) midsum += __shfl_xor_sync(FULL_MASK, midsum, o);

    volatile float* partial = (volatile float*)g_partial;
    if (lane == 0) {
        int tag0 = tb[0];
        int tend = tb[len - 1];
        float gold = trans[START * TAGS + tag0] + fb[tag0]   // begin
                   + trans[tend * TAGS + STOP]               // end
                   + midsum;                                 // middle
        partial[b] = fwd - gold;
    }

    // ---- last-block-done fused reduction (deterministic fixed-order sum)
    __threadfence();
    int old = 0;
    if (lane == 0) old = atomicAdd(&g_count, 1);
    old = __shfl_sync(FULL_MASK, old, 0);
    if (old == B - 1) {
        __threadfence();
        double acc = 0.0;
        for (int i = lane; i < B; i += 32)
            acc += (double)partial[i];
#pragma unroll
        for (int o = 16; o; o >>= 1)
            acc += __shfl_xor_sync(FULL_MASK, acc, o);
        if (lane == 0) {
            out[0] = (float)acc;
            g_count = 0;   // reset for next graph replay
        }
    }
}

extern "C" void kernel_launch(void* const* d_in, const int* in_sizes, int n_in,
                              void* d_out, int out_size)
{
    const float* feats = (const float*)d_in[0];
    const float* trans = (const float*)d_in[1];
    const int*   tags  = (const int*)d_in[2];
    const int*   lens  = (const int*)d_in[3];
    float* out = (float*)d_out;

    int B = in_sizes[3];                  // word_seq_lens: (B,)
    int L = in_sizes[2] / B;              // tags: (B, L)

    crf_nll_kernel<<<B, 32>>>(feats, trans, tags, lens, out, B, L);
}